// round 12
// baseline (speedup 1.0000x reference)
#include <cuda_runtime.h>
#include <cuda_bf16.h>
#include <math.h>

// Problem constants (fixed by the reference)
#define BB   8192
#define DIN  2048
#define HH   1024
#define VV   6
#define TT   6

// ---------------------------------------------------------------------------
// Scratch: static __device__ arrays (no runtime allocation allowed)
// ---------------------------------------------------------------------------
__device__ float g_h [BB * HH];   // GRU hidden state
__device__ float g_zb[BB * HH];   // z pre-activation -> z
__device__ float g_rb[BB * HH];   // r pre-activation -> r*h
__device__ float g_hp[BB * HH];   // h_tilde pre-activation
__device__ float g_Pz[(VV + 1) * HH];   // prev-contribution tables (row VV = start_embed)
__device__ float g_Pr[(VV + 1) * HH];
__device__ float g_Ph[(VV + 1) * HH];
__device__ int   g_tok[BB];
__device__ float g_rc [BB];
__device__ float g_nt [BB];

// ---------------------------------------------------------------------------
// Table builder: P*[v][j] = sum_k e_v[k] * W*[k][j]
// ---------------------------------------------------------------------------
__global__ void build_tables(const float* __restrict__ W_tok,
                             const float* __restrict__ b_tok,
                             const float* __restrict__ start_embed,
                             const float* __restrict__ Wz,
                             const float* __restrict__ Wr,
                             const float* __restrict__ Wh)
{
    int v = blockIdx.y;                       // 0..VV
    int j = blockIdx.x * blockDim.x + threadIdx.x;  // 0..HH-1
    float az = 0.f, ar = 0.f, ah = 0.f;
    for (int k = 0; k < HH; k++) {
        float e = (v < VV) ? (W_tok[v * HH + k] + b_tok[k]) : start_embed[k];
        az += e * Wz[k * HH + j];
        ar += e * Wr[k * HH + j];
        ah += e * Wh[k * HH + j];
    }
    g_Pz[v * HH + j] = az;
    g_Pr[v * HH + j] = ar;
    g_Ph[v * HH + j] = ah;
}

__global__ void init_state()
{
    int b = blockIdx.x * blockDim.x + threadIdx.x;
    if (b < BB) {
        g_tok[b] = VV;      // sentinel: start_embed row of the P tables
        g_rc[b]  = 1.f;
        g_nt[b]  = 0.f;
    }
}

// ---------------------------------------------------------------------------
// SGEMM: C[M,N] = A[M,K] @ B[K,N] (+bias). 128x128 tile, BK=8, 8x8/thread,
// 256 threads, double-buffered shared, PACKED fp32 (fma.rn.f32x2 / FFMA2).
// A smem tile stored DUPLICATED so one LDS.128 yields two (a,a) broadcast
// pairs; B pairs are naturally adjacent. 32 FFMA2 per k instead of 64 FFMA.
// ---------------------------------------------------------------------------
union F4U { float4 f; unsigned long long u[2]; };

__global__ __launch_bounds__(256, 2)
void sgemm128(const float* __restrict__ A, const float* __restrict__ Bm,
              const float* __restrict__ bias, float* __restrict__ C,
              int K, int lda, int ldb, int ldc)
{
    __shared__ float As2[2][8][256];   // duplicated: As2[buf][k][2r]=As2[..][2r+1]=A[r][k]
    __shared__ float Bs [2][8][128];

    const int tid = threadIdx.x;
    const int tx  = tid & 15;         // 0..15 -> 8 cols each
    const int ty  = tid >> 4;         // 0..15 -> 8 rows each
    const int rowBase = blockIdx.y * 128;
    const int colBase = blockIdx.x * 128;

    const int aRow = tid >> 1;        // 0..127
    const int aCol = (tid & 1) * 4;   // 0 or 4
    const int bRow = tid >> 5;        // 0..7
    const int bCol = (tid & 31) * 4;  // 0..124

    const float* Aptr = A + (size_t)(rowBase + aRow) * lda + aCol;
    const float* Bptr = Bm + (size_t)bRow * ldb + colBase + bCol;

    unsigned long long acc2[8][4];    // acc2[i][j] packs C[row i][col 2j], [col 2j+1]
#pragma unroll
    for (int i = 0; i < 8; i++)
#pragma unroll
        for (int j = 0; j < 4; j++) acc2[i][j] = 0ull;

    // preload tile 0
    float4 a4 = *(const float4*)Aptr;
    float4 b4 = *(const float4*)Bptr;
    {
        float2 d0 = make_float2(a4.x, a4.x);
        float2 d1 = make_float2(a4.y, a4.y);
        float2 d2 = make_float2(a4.z, a4.z);
        float2 d3 = make_float2(a4.w, a4.w);
        *(float2*)&As2[0][aCol + 0][2 * aRow] = d0;
        *(float2*)&As2[0][aCol + 1][2 * aRow] = d1;
        *(float2*)&As2[0][aCol + 2][2 * aRow] = d2;
        *(float2*)&As2[0][aCol + 3][2 * aRow] = d3;
        *(float4*)&Bs[0][bRow][bCol] = b4;
    }
    __syncthreads();

    const int nTiles = K >> 3;
    int cur = 0;
    for (int kt = 0; kt < nTiles; kt++) {
        if (kt + 1 < nTiles) {
            a4 = *(const float4*)(Aptr + (kt + 1) * 8);
            b4 = *(const float4*)(Bptr + (size_t)(kt + 1) * 8 * ldb);
        }
#pragma unroll
        for (int k = 0; k < 8; k++) {
            F4U ad0, ad1, ad2, ad3, bu0, bu1;
            ad0.f = *(const float4*)&As2[cur][k][ty * 16 + 0];
            ad1.f = *(const float4*)&As2[cur][k][ty * 16 + 4];
            ad2.f = *(const float4*)&As2[cur][k][ty * 16 + 8];
            ad3.f = *(const float4*)&As2[cur][k][ty * 16 + 12];
            bu0.f = *(const float4*)&Bs[cur][k][tx * 8];
            bu1.f = *(const float4*)&Bs[cur][k][tx * 8 + 4];
            unsigned long long a2[8] = { ad0.u[0], ad0.u[1], ad1.u[0], ad1.u[1],
                                         ad2.u[0], ad2.u[1], ad3.u[0], ad3.u[1] };
            unsigned long long b2[4] = { bu0.u[0], bu0.u[1], bu1.u[0], bu1.u[1] };
#pragma unroll
            for (int i = 0; i < 8; i++)
#pragma unroll
                for (int j = 0; j < 4; j++)
                    asm("fma.rn.f32x2 %0, %1, %2, %0;"
                        : "+l"(acc2[i][j]) : "l"(a2[i]), "l"(b2[j]));
        }
        if (kt + 1 < nTiles) {
            int nxt = cur ^ 1;
            float2 d0 = make_float2(a4.x, a4.x);
            float2 d1 = make_float2(a4.y, a4.y);
            float2 d2 = make_float2(a4.z, a4.z);
            float2 d3 = make_float2(a4.w, a4.w);
            *(float2*)&As2[nxt][aCol + 0][2 * aRow] = d0;
            *(float2*)&As2[nxt][aCol + 1][2 * aRow] = d1;
            *(float2*)&As2[nxt][aCol + 2][2 * aRow] = d2;
            *(float2*)&As2[nxt][aCol + 3][2 * aRow] = d3;
            *(float4*)&Bs[nxt][bRow][bCol] = b4;
            __syncthreads();
            cur = nxt;
        }
    }

#pragma unroll
    for (int i = 0; i < 8; i++) {
        int row = rowBase + ty * 8 + i;
        float* Cp = C + (size_t)row * ldc + colBase + tx * 8;
        F4U lo, hi;
        lo.u[0] = acc2[i][0]; lo.u[1] = acc2[i][1];
        hi.u[0] = acc2[i][2]; hi.u[1] = acc2[i][3];
        float4 o0 = lo.f, o1 = hi.f;
        if (bias) {
            const float* bp = bias + colBase + tx * 8;
            o0.x += bp[0]; o0.y += bp[1]; o0.z += bp[2]; o0.w += bp[3];
            o1.x += bp[4]; o1.y += bp[5]; o1.z += bp[6]; o1.w += bp[7];
        }
        *(float4*)(Cp + 0) = o0;
        *(float4*)(Cp + 4) = o1;
    }
}

// ---------------------------------------------------------------------------
// Elementwise passes
// ---------------------------------------------------------------------------
__device__ __forceinline__ float sigmoidf(float x) { return 1.f / (1.f + expf(-x)); }

__global__ void zr_act(const float* __restrict__ bz, const float* __restrict__ br)
{
    int idx = blockIdx.x * blockDim.x + threadIdx.x;   // over BB*HH/4
    int b  = idx >> 8;          // HH/4 = 256
    int j4 = idx & 255;
    int t  = g_tok[b];

    float4 zp = ((const float4*)g_zb)[idx];
    float4 rp = ((const float4*)g_rb)[idx];
    float4 hv = ((const float4*)g_h )[idx];
    float4 pz = ((const float4*)g_Pz)[t * 256 + j4];
    float4 pr = ((const float4*)g_Pr)[t * 256 + j4];
    float4 vz = ((const float4*)bz)[j4];
    float4 vr = ((const float4*)br)[j4];

    float4 z, r;
    z.x = sigmoidf(zp.x + pz.x + vz.x);
    z.y = sigmoidf(zp.y + pz.y + vz.y);
    z.z = sigmoidf(zp.z + pz.z + vz.z);
    z.w = sigmoidf(zp.w + pz.w + vz.w);
    r.x = sigmoidf(rp.x + pr.x + vr.x) * hv.x;
    r.y = sigmoidf(rp.y + pr.y + vr.y) * hv.y;
    r.z = sigmoidf(rp.z + pr.z + vr.z) * hv.z;
    r.w = sigmoidf(rp.w + pr.w + vr.w) * hv.w;

    ((float4*)g_zb)[idx] = z;   // now holds z
    ((float4*)g_rb)[idx] = r;   // now holds r*h
}

// h = (1-z)*h + z*tanh(hpre + Ph[tok] + bh)
__global__ void gru_update(const float* __restrict__ bh)
{
    int idx = blockIdx.x * blockDim.x + threadIdx.x;
    int b  = idx >> 8;
    int j4 = idx & 255;
    int t  = g_tok[b];

    float4 hp = ((const float4*)g_hp)[idx];
    float4 ph = ((const float4*)g_Ph)[t * 256 + j4];
    float4 vb = ((const float4*)bh)[j4];
    float4 z  = ((const float4*)g_zb)[idx];
    float4 h  = ((const float4*)g_h )[idx];

    float4 o;
    o.x = (1.f - z.x) * h.x + z.x * tanhf(hp.x + ph.x + vb.x);
    o.y = (1.f - z.y) * h.y + z.y * tanhf(hp.y + ph.y + vb.y);
    o.z = (1.f - z.z) * h.z + z.z * tanhf(hp.z + ph.z + vb.z);
    o.w = (1.f - z.w) * h.w + z.w * tanhf(hp.w + ph.w + vb.w);
    ((float4*)g_h)[idx] = o;
}

// ---------------------------------------------------------------------------
// Decode: one warp per batch row. argmax(logits + gumbel), no softmax needed.
// ---------------------------------------------------------------------------
__global__ void decode(const float* __restrict__ W_out,
                       const float* __restrict__ b_out,
                       const float* __restrict__ u_noise,
                       float* __restrict__ out_msg,
                       float* __restrict__ out_logits,
                       int t)
{
    int warp = (blockIdx.x * blockDim.x + threadIdx.x) >> 5;
    int lane = threadIdx.x & 31;
    if (warp >= BB) return;

    const float* hrow = g_h + (size_t)warp * HH;
    float acc[VV];
#pragma unroll
    for (int v = 0; v < VV; v++) acc[v] = 0.f;

    for (int j = lane; j < HH; j += 32) {
        float hv = hrow[j];
        const float* w = W_out + j * VV;
#pragma unroll
        for (int v = 0; v < VV; v++) acc[v] += hv * w[v];
    }
#pragma unroll
    for (int v = 0; v < VV; v++)
#pragma unroll
        for (int off = 16; off; off >>= 1)
            acc[v] += __shfl_xor_sync(0xFFFFFFFFu, acc[v], off);

    if (lane == 0) {
        float rc = g_rc[warp];
        g_nt[warp] += rc;                 // nt uses rc at step start

        const float eps = 1e-10f;
        float best = -1e30f;
        int amax = 0;
        float logits[VV];
#pragma unroll
        for (int v = 0; v < VV; v++) {
            float lg = acc[v] + b_out[v];
            logits[v] = lg;
            float u = u_noise[t * (BB * VV) + warp * VV + v];
            float g = -logf(-logf(u + eps) + eps);
            float a = lg + g;
            if (a > best) { best = a; amax = v; }   // first-max on ties
        }
#pragma unroll
        for (int v = 0; v < VV; v++) {
            out_logits[t * (BB * VV) + warp * VV + v] = logits[v];
            out_msg[warp * (TT * VV) + t * VV + v] = (v == amax) ? rc : 0.f;
        }
        g_tok[warp] = amax;
        if (amax == VV - 1) g_rc[warp] = 0.f;   // STOP symbol
    }
}

__global__ void write_ntokens(float* __restrict__ out_nt)
{
    int b = blockIdx.x * blockDim.x + threadIdx.x;
    if (b < BB) out_nt[b] = g_nt[b];
}

// ---------------------------------------------------------------------------
// kernel_launch
// ---------------------------------------------------------------------------
extern "C" void kernel_launch(void* const* d_in, const int* in_sizes, int n_in,
                              void* d_out, int out_size)
{
    const float* x          = (const float*)d_in[0];
    const float* u_noise    = (const float*)d_in[1];
    const float* W_enc      = (const float*)d_in[2];
    const float* b_enc      = (const float*)d_in[3];
    const float* start_emb  = (const float*)d_in[4];
    const float* W_tok      = (const float*)d_in[5];
    const float* b_tok      = (const float*)d_in[6];
    const float* Wz         = (const float*)d_in[7];
    const float* bz         = (const float*)d_in[8];
    const float* Wr         = (const float*)d_in[9];
    const float* br         = (const float*)d_in[10];
    const float* Wh         = (const float*)d_in[11];
    const float* bh         = (const float*)d_in[12];
    const float* W_out      = (const float*)d_in[13];
    const float* b_out      = (const float*)d_in[14];

    float* out      = (float*)d_out;
    float* out_msg  = out;                                 // B*T*V
    float* out_log  = out + (size_t)BB * TT * VV;          // T*B*V
    float* out_nt   = out + (size_t)BB * TT * VV + (size_t)TT * BB * VV;

    float *p_h, *p_zb, *p_rb, *p_hp;
    cudaGetSymbolAddress((void**)&p_h,  g_h);
    cudaGetSymbolAddress((void**)&p_zb, g_zb);
    cudaGetSymbolAddress((void**)&p_rb, g_rb);
    cudaGetSymbolAddress((void**)&p_hp, g_hp);

    build_tables<<<dim3(HH / 256, VV + 1), 256>>>(W_tok, b_tok, start_emb, Wz, Wr, Wh);
    init_state<<<(BB + 255) / 256, 256>>>();

    // encoder: h0 = x @ W_enc + b_enc
    sgemm128<<<dim3(HH / 128, BB / 128), 256>>>(x, W_enc, b_enc, p_h,
                                                DIN, DIN, HH, HH);

    const dim3 ggrid(HH / 128, BB / 128);
    const int ew_blocks = (BB * HH / 4) / 256;   // 8192

    for (int t = 0; t < TT; t++) {
        // z/r pre-activations: h @ W*_bottom  (bottom halves of (2H,H) matrices)
        sgemm128<<<ggrid, 256>>>(p_h, Wz + (size_t)HH * HH, nullptr, p_zb,
                                 HH, HH, HH, HH);
        sgemm128<<<ggrid, 256>>>(p_h, Wr + (size_t)HH * HH, nullptr, p_rb,
                                 HH, HH, HH, HH);
        zr_act<<<ew_blocks, 256>>>(bz, br);
        // h_tilde pre-activation: (r*h) @ Wh_bottom
        sgemm128<<<ggrid, 256>>>(p_rb, Wh + (size_t)HH * HH, nullptr, p_hp,
                                 HH, HH, HH, HH);
        gru_update<<<ew_blocks, 256>>>(bh);
        decode<<<(BB * 32) / 256, 256>>>(W_out, b_out, u_noise, out_msg, out_log, t);
    }
    write_ntokens<<<(BB + 255) / 256, 256>>>(out_nt);
}